// round 14
// baseline (speedup 1.0000x reference)
#include <cuda_runtime.h>
#include <cuda_bf16.h>
#include <cstdint>

typedef unsigned long long ull;

#define CL 512
#define CB 64
#define CD 512
#define CLB (CL*CB)

// ---------------- scratch (static device allocations only) ----------------
__device__ float g_bufA[CLB*CD];              // activations ping (64 MB)
__device__ float g_bufB[CLB*CD];              // activations pong (64 MB)
__device__ float g_gx[(size_t)CLB*3*CD];      // gate pre-activations (192 MB)
__device__ __nv_bfloat16 g_chi[2][CB*CD];     // recurrent state bf16 hi, ping-pong
__device__ __nv_bfloat16 g_clo[2][CB*CD];     // recurrent state bf16 lo
__device__ float g_cfp[CB*CD];                // fp32 carry across scan launches
__device__ int   g_tok[CLB];
__device__ unsigned g_flag[4][32];            // per-(bg, d-group) step-completion flags
// bf16 split buffers for GEMM
__device__ ull g_Ahi[(size_t)CLB*CD/4];       // [32768,512] bf16
__device__ ull g_Alo[(size_t)CLB*CD/4];
__device__ ull g_Wthi[(size_t)4*1536*512/4];  // [4][1536][512] bf16 (W transposed)
__device__ ull g_Wtlo[(size_t)4*1536*512/4];

// ---------------- helpers ----------------
__device__ __forceinline__ unsigned ldacq(const unsigned* p){
    unsigned v; asm volatile("ld.acquire.gpu.u32 %0, [%1];" : "=r"(v) : "l"(p) : "memory"); return v;
}
__device__ __forceinline__ void red_rel_add(unsigned* p, unsigned v){
    asm volatile("red.add.release.gpu.u32 [%0], %1;" :: "l"(p), "r"(v) : "memory");
}
__device__ __forceinline__ float sigmoidf_(float x){ return 1.0f / (1.0f + __expf(-x)); }
__device__ __forceinline__ uint32_t smem_u32(const void* p){
    uint32_t a; asm("{ .reg .u64 t; cvta.to.shared.u64 t, %1; cvt.u32.u64 %0, t; }" : "=r"(a) : "l"(p));
    return a;
}
__device__ __forceinline__ void cpasync16(uint32_t dst, const void* src){
    asm volatile("cp.async.cg.shared.global [%0], [%1], 16;" :: "r"(dst), "l"(src));
}
__device__ __forceinline__ void cp_commit(){ asm volatile("cp.async.commit_group;" ::: "memory"); }
__device__ __forceinline__ void ldsm4(uint32_t addr, uint32_t* r){
    asm volatile("ldmatrix.sync.aligned.m8n8.x4.shared.b16 {%0,%1,%2,%3}, [%4];"
        : "=r"(r[0]),"=r"(r[1]),"=r"(r[2]),"=r"(r[3]) : "r"(addr));
}
__device__ __forceinline__ void ldsm2(uint32_t addr, uint32_t* r){
    asm volatile("ldmatrix.sync.aligned.m8n8.x2.shared.b16 {%0,%1}, [%2];"
        : "=r"(r[0]),"=r"(r[1]) : "r"(addr));
}
__device__ __forceinline__ void mma16816(float* d, const uint32_t* a, const uint32_t* b){
    asm volatile("mma.sync.aligned.m16n8k16.row.col.f32.bf16.bf16.f32 "
        "{%0,%1,%2,%3}, {%4,%5,%6,%7}, {%8,%9}, {%0,%1,%2,%3};"
        : "+f"(d[0]),"+f"(d[1]),"+f"(d[2]),"+f"(d[3])
        : "r"(a[0]),"r"(a[1]),"r"(a[2]),"r"(a[3]), "r"(b[0]),"r"(b[1]));
}

// ---------------- prep ----------------
__global__ void prep_kernel(const int* __restrict__ xs32) {
    __shared__ unsigned s_nz;
    int tid = threadIdx.x;
    if (tid == 0) s_nz = 0u;
    __syncthreads();
    unsigned nz = 0u;
    for (int i = tid; i < 1024; i += blockDim.x) nz |= (unsigned)xs32[2*i + 1];
    if (nz) atomicOr(&s_nz, 1u);
    __syncthreads();
    bool is64 = (s_nz == 0u);

    int stride = gridDim.x * blockDim.x;
    int gid = blockIdx.x * blockDim.x + tid;
    if (is64) {
        const long long* x64 = (const long long*)xs32;
        for (int i = gid; i < CLB; i += stride) g_tok[i] = (int)x64[i];
    } else {
        for (int i = gid; i < CLB; i += stride) g_tok[i] = xs32[i];
    }
    __nv_bfloat16 z = __float2bfloat16(0.0f);
    for (int i = gid; i < CB*CD; i += stride) {
        g_chi[0][i] = z; g_clo[0][i] = z; g_cfp[i] = 0.0f;
    }
    if (gid < 4*32) ((unsigned*)g_flag)[gid] = 0u;
}

// ---------------- embedding gather ----------------
__global__ void embed_kernel(const float* __restrict__ emb) {
    int row = blockIdx.x;
    int tok = g_tok[row];
    const float4* s = (const float4*)(emb + (size_t)tok * CD);
    float4* d = (float4*)(g_bufA + (size_t)row * CD);
    d[threadIdx.x] = s[threadIdx.x];
}

// ---------------- W transpose + bf16 hi/lo split (for GEMM) ----------------
__global__ void wsplit_kernel(const float* __restrict__ W) {
    __shared__ float t[32][33];
    int layer = blockIdx.z;
    int nt = blockIdx.x;
    int kt = blockIdx.y;
    int tx = threadIdx.x;
    __nv_bfloat16* Whi = (__nv_bfloat16*)g_Wthi;
    __nv_bfloat16* Wlo = (__nv_bfloat16*)g_Wtlo;
    for (int i = threadIdx.y; i < 32; i += 8)
        t[i][tx] = W[(size_t)layer*512*1536 + (size_t)(kt*32 + i)*1536 + nt*32 + tx];
    __syncthreads();
    for (int i = threadIdx.y; i < 32; i += 8) {
        float v = t[tx][i];
        __nv_bfloat16 h = __float2bfloat16(v);
        __nv_bfloat16 l = __float2bfloat16(v - __bfloat162float(h));
        size_t o = ((size_t)layer*1536 + nt*32 + i)*512 + kt*32 + tx;
        Whi[o] = h; Wlo[o] = l;
    }
}

// ---------------- A bf16 hi/lo split (layer-0 input only) ----------------
__global__ void asplit_kernel(const float* __restrict__ A) {
    size_t i = (size_t)blockIdx.x * blockDim.x + threadIdx.x;
    float4 v = ((const float4*)A)[i];
    __nv_bfloat16 h0 = __float2bfloat16(v.x), h1 = __float2bfloat16(v.y);
    __nv_bfloat16 h2 = __float2bfloat16(v.z), h3 = __float2bfloat16(v.w);
    __nv_bfloat162* Hi = (__nv_bfloat162*)g_Ahi;
    __nv_bfloat162* Lo = (__nv_bfloat162*)g_Alo;
    Hi[2*i]   = __nv_bfloat162(h0, h1);
    Hi[2*i+1] = __nv_bfloat162(h2, h3);
    Lo[2*i]   = __nv_bfloat162(__float2bfloat16(v.x - __bfloat162float(h0)),
                               __float2bfloat16(v.y - __bfloat162float(h1)));
    Lo[2*i+1] = __nv_bfloat162(__float2bfloat16(v.z - __bfloat162float(h2)),
                               __float2bfloat16(v.w - __bfloat162float(h3)));
}

// ---------------- mma.sync GEMM (3-term bf16 split) — proven R6 version ----------------
#define STAGE    65536
#define O_AHI    0
#define O_ALO    16384
#define O_WHI    32768
#define O_WLO    49152
#define GEMM_SMEM (2*STAGE + 1024)

__device__ __forceinline__ void load_stage(uint32_t sbuf,
        const __nv_bfloat16* Ah, const __nv_bfloat16* Al,
        const __nv_bfloat16* Wh, const __nv_bfloat16* Wl, int kc, int tid) {
    #pragma unroll
    for (int it = 0; it < 4; it++) {
        int c = tid + it*256;
        int row = c >> 3, seg = c & 7;
        uint32_t off = row*128 + seg*16;
        uint32_t sw  = off ^ ((off >> 3) & 0x70);
        size_t goff = (size_t)row*512 + kc*64 + seg*8;
        cpasync16(sbuf + O_AHI + sw, Ah + goff);
        cpasync16(sbuf + O_ALO + sw, Al + goff);
        cpasync16(sbuf + O_WHI + sw, Wh + goff);
        cpasync16(sbuf + O_WLO + sw, Wl + goff);
    }
}

__global__ __launch_bounds__(256, 1)
void mma_gemm_kernel(const float* __restrict__ bias, float* __restrict__ C, int layer) {
    extern __shared__ char gsm[];
    __shared__ float sbias[128];

    int tid = threadIdx.x;
    int lane = tid & 31;
    int warp = tid >> 5;
    int wm = warp >> 1;
    int wn = warp & 1;
    int bn = blockIdx.x;
    int bm = blockIdx.y;
    int m0 = bm * 128, n0 = bn * 128;

    uint32_t dynbase = (smem_u32(gsm) + 1023u) & ~1023u;

    const __nv_bfloat16* Ah = (const __nv_bfloat16*)g_Ahi + (size_t)m0 * 512;
    const __nv_bfloat16* Al = (const __nv_bfloat16*)g_Alo + (size_t)m0 * 512;
    const __nv_bfloat16* Wh = (const __nv_bfloat16*)g_Wthi + ((size_t)layer*1536 + n0) * 512;
    const __nv_bfloat16* Wl = (const __nv_bfloat16*)g_Wtlo + ((size_t)layer*1536 + n0) * 512;

    if (tid < 128) sbias[tid] = bias[n0 + tid];

    int a_rowin = (lane & 7) + ((lane >> 3) & 1) * 8;
    uint32_t a_kb_lane = (uint32_t)(lane >> 4) * 16;
    uint32_t a_rowb[2]; uint32_t a_s[2];
    #pragma unroll
    for (int t = 0; t < 2; t++) {
        uint32_t rb = (uint32_t)(wm*32 + t*16 + a_rowin) * 128;
        a_rowb[t] = rb;
        a_s[t] = (rb >> 3) & 0x70;
    }
    int b_rowin = lane & 7;
    uint32_t b_kb_lane = (uint32_t)((lane >> 3) & 1) * 16;
    uint32_t b_rowb[8]; uint32_t b_s[8];
    #pragma unroll
    for (int bt = 0; bt < 8; bt++) {
        uint32_t rb = (uint32_t)(wn*64 + bt*8 + b_rowin) * 128;
        b_rowb[bt] = rb;
        b_s[bt] = (rb >> 3) & 0x70;
    }

    float acc[2][8][4];
    #pragma unroll
    for (int t = 0; t < 2; t++)
        #pragma unroll
        for (int bt = 0; bt < 8; bt++)
            #pragma unroll
            for (int q = 0; q < 4; q++) acc[t][bt][q] = 0.0f;

    load_stage(dynbase, Ah, Al, Wh, Wl, 0, tid);
    cp_commit();

    for (int kc = 0; kc < 8; kc++) {
        uint32_t cbuf = dynbase + (kc & 1) * STAGE;
        if (kc < 7) {
            load_stage(dynbase + ((kc + 1) & 1) * STAGE, Ah, Al, Wh, Wl, kc + 1, tid);
            cp_commit();
            asm volatile("cp.async.wait_group 1;" ::: "memory");
        } else {
            asm volatile("cp.async.wait_group 0;" ::: "memory");
        }
        __syncthreads();

        #pragma unroll
        for (int ks = 0; ks < 4; ks++) {
            uint32_t akb = (uint32_t)ks*32 + a_kb_lane;
            uint32_t bkb = (uint32_t)ks*32 + b_kb_lane;
            uint32_t ah[2][4], al[2][4];
            #pragma unroll
            for (int t = 0; t < 2; t++) {
                uint32_t ao = a_rowb[t] + (akb ^ a_s[t]);
                ldsm4(cbuf + O_AHI + ao, ah[t]);
                ldsm4(cbuf + O_ALO + ao, al[t]);
            }
            uint32_t bh[8][2], bl[8][2];
            #pragma unroll
            for (int bt = 0; bt < 8; bt++) {
                uint32_t bo = b_rowb[bt] + (bkb ^ b_s[bt]);
                ldsm2(cbuf + O_WHI + bo, bh[bt]);
                ldsm2(cbuf + O_WLO + bo, bl[bt]);
            }
            #pragma unroll
            for (int t = 0; t < 2; t++)
                #pragma unroll
                for (int bt = 0; bt < 8; bt++) {
                    mma16816(acc[t][bt], ah[t], bh[bt]);
                    mma16816(acc[t][bt], ah[t], bl[bt]);
                    mma16816(acc[t][bt], al[t], bh[bt]);
                }
        }
        __syncthreads();
    }

    int r_in = lane >> 2;
    int c_in = 2 * (lane & 3);
    #pragma unroll
    for (int t = 0; t < 2; t++) {
        int row = m0 + wm*32 + t*16 + r_in;
        #pragma unroll
        for (int bt = 0; bt < 8; bt++) {
            int col = wn*64 + bt*8 + c_in;
            float b0 = sbias[col], b1 = sbias[col + 1];
            float2 o0 = make_float2(acc[t][bt][0] + b0, acc[t][bt][1] + b1);
            float2 o1 = make_float2(acc[t][bt][2] + b0, acc[t][bt][3] + b1);
            *(float2*)(C + (size_t)row * 1536 + n0 + col) = o0;
            *(float2*)(C + (size_t)(row + 8) * 1536 + n0 + col) = o1;
        }
    }
}

// ---------------- recurrent scan v8: dual-chain interleave (2 batch-groups per block) ----------------
// 64 blocks = 2 bg-pairs x 32 d-groups. Chain A = bg pair*2, chain B = pair*2+1.
// 256 threads = 8 warps: wn = warp&3 (8 cols), wk = warp>>2 (256 k). W slice shared by chains.
#define S_WHI 0
#define S_WLO (S_WHI + 32*1040)
#define S_CAH (S_WLO + 32*1040)
#define S_CAL (S_CAH + 16*1040)
#define S_CBH (S_CAL + 16*1040)
#define S_CBL (S_CBH + 16*1040)
#define S_RED (S_CBL + 16*1040)
#define SCAN_SMEM (S_RED + 2*16*33*4)

__device__ __forceinline__ void stage_c(uint32_t sb, uint32_t dstH, uint32_t dstL,
                                        int p, int r0, int tid) {
    const char* srcH = (const char*)(g_chi[p]) + (size_t)r0 * 1024;
    const char* srcL = (const char*)(g_clo[p]) + (size_t)r0 * 1024;
    #pragma unroll
    for (int it = 0; it < 4; it++) {
        int idx = tid + it*256;            // 0..1023
        int row = idx >> 6, seg = idx & 63;
        uint32_t d = (uint32_t)row*1040 + (uint32_t)seg*16;
        size_t   s = (size_t)row*1024 + (size_t)seg*16;
        cpasync16(sb + dstH + d, srcH + s);
        cpasync16(sb + dstL + d, srcL + s);
    }
    cp_commit();
}

__global__ __launch_bounds__(256, 1)
void scan_kernel(const float* __restrict__ x_in, const float* __restrict__ gx,
                 const float* __restrict__ Wc, float* __restrict__ h_out,
                 int rev, unsigned cnt_base, int do_split) {
    extern __shared__ char smem[];
    uint32_t sb = smem_u32(smem);
    float* red = (float*)(smem + S_RED);

    int tid = threadIdx.x;
    int lane = tid & 31;
    int warp = tid >> 5;
    int wn = warp & 3;
    int wk = warp >> 2;
    int bp = blockIdx.x >> 5;      // 0..1 (bg pair)
    int dg = blockIdx.x & 31;      // 0..31
    int bgA = bp * 2, bgB = bp * 2 + 1;
    int r0A = bgA * 16, r0B = bgB * 16;
    int d0 = dg * 16;

    // ---- fill W slice (32 cols x 512 k), bf16 hi/lo, padded rows (once)
    {
        __nv_bfloat16* wh = (__nv_bfloat16*)(smem + S_WHI);
        __nv_bfloat16* wl = (__nv_bfloat16*)(smem + S_WLO);
        for (int idx = tid; idx < 32*512; idx += 256) {
            int col = idx >> 9, k = idx & 511;
            int gcol = (col < 16) ? (d0 + col) : (512 + d0 + col - 16);
            float v = Wc[(size_t)k * 1024 + gcol];
            __nv_bfloat16 h = __float2bfloat16(v);
            wh[col*520 + k] = h;
            wl[col*520 + k] = __float2bfloat16(v - __bfloat162float(h));
        }
    }

    // ldmatrix lane addressing
    int a_rowin = (lane & 7) + ((lane >> 3) & 1) * 8;
    uint32_t a_off = (uint32_t)a_rowin*1040 + (uint32_t)(lane >> 4)*16 + (uint32_t)wk*512;
    uint32_t aAH = sb + S_CAH + a_off, aAL = sb + S_CAL + a_off;
    uint32_t aBH = sb + S_CBH + a_off, aBL = sb + S_CBL + a_off;
    int b_rowin = lane & 7;
    uint32_t b_kb = (uint32_t)((lane >> 3) & 1) * 16;
    uint32_t bH0 = sb + S_WHI + (uint32_t)(wn*8 + b_rowin)*1040 + b_kb + (uint32_t)wk*512;
    uint32_t bL0 = sb + S_WLO + (uint32_t)(wn*8 + b_rowin)*1040 + b_kb + (uint32_t)wk*512;

    // epilogue mapping
    int erow = tid >> 4;
    int ej   = tid & 15;
    int ebA  = r0A + erow, ebB = r0B + erow;
    int ed   = d0 + ej;
    float cregA = g_cfp[(size_t)ebA * 512 + ed];
    float cregB = g_cfp[(size_t)ebB * 512 + ed];

    __nv_bfloat16* Ahi = (__nv_bfloat16*)g_Ahi;
    __nv_bfloat16* Alo = (__nv_bfloat16*)g_Alo;

    int r_in = lane >> 2;
    int c_in = 2 * (lane & 3);
    int rcol = wn*8 + c_in;
    float* rp = red + (size_t)wk * 16 * 33;

    __syncthreads();

    // ---- prologue: poll A(0), stage A(0)
    {
        unsigned tgt = cnt_base;
        if (warp == 0) {
            while (__ballot_sync(0xffffffffu, ldacq(&g_flag[bgA][lane]) < tgt) != 0u) {}
        }
        __syncthreads();
        stage_c(sb, S_CAH, S_CAL, 0, r0A, tid);
    }

    for (int t = 0; t < 512; ++t) {
        int tt = rev ? (511 - t) : t;
        int p  = t & 1;
        unsigned tgt  = cnt_base + (unsigned)t * 256u;

        // ======== chain A ========
        // wait A staged (only A group pending for this thread)
        asm volatile("cp.async.wait_group 0;" ::: "memory");
        __syncthreads();

        // poll B(t) + stage B(t) — overlaps with A matvec below
        if (warp == 0) {
            while (__ballot_sync(0xffffffffu, ldacq(&g_flag[bgB][lane]) < tgt) != 0u) {}
        }
        __syncthreads();
        stage_c(sb, S_CBH, S_CBL, p, r0B, tid);

        size_t growA = (size_t)tt * CB + ebA;
        float giA = gx[growA*1536 + ed];
        float gfA = gx[growA*1536 + 512 + ed];
        float gcA = gx[growA*1536 + 1024 + ed];
        float xvA = x_in[growA*512 + ed];

        {
            float accA[4] = {0,0,0,0}, accB[4] = {0,0,0,0}, accC[4] = {0,0,0,0};
            uint32_t aH = aAH, aL = aAL, bH = bH0, bL = bL0;
            #pragma unroll
            for (int kt = 0; kt < 16; kt++) {
                uint32_t ah[4], al[4], bh[2], bl[2];
                ldsm4(aH, ah); ldsm4(aL, al);
                ldsm2(bH, bh); ldsm2(bL, bl);
                mma16816(accA, ah, bh);
                mma16816(accB, ah, bl);
                mma16816(accC, al, bh);
                aH += 32; aL += 32; bH += 32; bL += 32;
            }
            rp[(r_in    )*33 + rcol    ] = accA[0] + accB[0] + accC[0];
            rp[(r_in    )*33 + rcol + 1] = accA[1] + accB[1] + accC[1];
            rp[(r_in + 8)*33 + rcol    ] = accA[2] + accB[2] + accC[2];
            rp[(r_in + 8)*33 + rcol + 1] = accA[3] + accB[3] + accC[3];
        }
        __syncthreads();

        {   // epilogue A
            float pre_i = red[erow*33 + ej]      + red[16*33 + erow*33 + ej];
            float pre_f = red[erow*33 + 16 + ej] + red[16*33 + erow*33 + 16 + ej];
            float iv = sigmoidf_(giA + pre_i);
            float fv = sigmoidf_(gfA + pre_f);
            float cn = iv * gcA + fv * cregA;
            cregA = cn;
            __nv_bfloat16 ch = __float2bfloat16(cn);
            g_chi[p ^ 1][(size_t)ebA * 512 + ed] = ch;
            g_clo[p ^ 1][(size_t)ebA * 512 + ed] = __float2bfloat16(cn - __bfloat162float(ch));
            red_rel_add(&g_flag[bgA][dg], 1u);

            float hv = tanhf(cn) + xvA;
            h_out[growA*512 + ed] = hv;
            if (t == 511) g_cfp[(size_t)ebA * 512 + ed] = cn;
            if (do_split) {
                __nv_bfloat16 hh = __float2bfloat16(hv);
                Ahi[growA*512 + ed] = hh;
                Alo[growA*512 + ed] = __float2bfloat16(hv - __bfloat162float(hh));
            }
        }

        // ======== chain B ========
        asm volatile("cp.async.wait_group 0;" ::: "memory");
        __syncthreads();

        // poll A(t+1) + stage A(t+1) — overlaps with B matvec below
        if (t < 511) {
            unsigned tgtA = cnt_base + (unsigned)(t + 1) * 256u;
            if (warp == 0) {
                while (__ballot_sync(0xffffffffu, ldacq(&g_flag[bgA][lane]) < tgtA) != 0u) {}
            }
            __syncthreads();
            stage_c(sb, S_CAH, S_CAL, p ^ 1, r0A, tid);
        }

        size_t growB = (size_t)tt * CB + ebB;
        float giB = gx[growB*1536 + ed];
        float gfB = gx[growB*1536 + 512 + ed];
        float gcB = gx[growB*1536 + 1024 + ed];
        float xvB = x_in[growB*512 + ed];

        {
            float accA[4] = {0,0,0,0}, accB[4] = {0,0,0,0}, accC[4] = {0,0,0,0};
            uint32_t aH = aBH, aL = aBL, bH = bH0, bL = bL0;
            #pragma unroll
            for (int kt = 0; kt < 16; kt++) {
                uint32_t ah[4], al[4], bh[2], bl[2];
                ldsm4(aH, ah); ldsm4(aL, al);
                ldsm2(bH, bh); ldsm2(bL, bl);
                mma16816(accA, ah, bh);
                mma16816(accB, ah, bl);
                mma16816(accC, al, bh);
                aH += 32; aL += 32; bH += 32; bL += 32;
            }
            rp[(r_in    )*33 + rcol    ] = accA[0] + accB[0] + accC[0];
            rp[(r_in    )*33 + rcol + 1] = accA[1] + accB[1] + accC[1];
            rp[(r_in + 8)*33 + rcol    ] = accA[2] + accB[2] + accC[2];
            rp[(r_in + 8)*33 + rcol + 1] = accA[3] + accB[3] + accC[3];
        }
        __syncthreads();

        {   // epilogue B
            float pre_i = red[erow*33 + ej]      + red[16*33 + erow*33 + ej];
            float pre_f = red[erow*33 + 16 + ej] + red[16*33 + erow*33 + 16 + ej];
            float iv = sigmoidf_(giB + pre_i);
            float fv = sigmoidf_(gfB + pre_f);
            float cn = iv * gcB + fv * cregB;
            cregB = cn;
            __nv_bfloat16 ch = __float2bfloat16(cn);
            g_chi[p ^ 1][(size_t)ebB * 512 + ed] = ch;
            g_clo[p ^ 1][(size_t)ebB * 512 + ed] = __float2bfloat16(cn - __bfloat162float(ch));
            red_rel_add(&g_flag[bgB][dg], 1u);

            float hv = tanhf(cn) + xvB;
            h_out[growB*512 + ed] = hv;
            if (t == 511) g_cfp[(size_t)ebB * 512 + ed] = cn;
            if (do_split) {
                __nv_bfloat16 hh = __float2bfloat16(hv);
                Ahi[growB*512 + ed] = hh;
                Alo[growB*512 + ed] = __float2bfloat16(hv - __bfloat162float(hh));
            }
        }
        __syncthreads();   // red reuse guard before next A matvec writes
    }
}

// ---------------- driver ----------------
extern "C" void kernel_launch(void* const* d_in, const int* in_sizes, int n_in,
                              void* d_out, int out_size) {
    const int*   xs   = (const int*)  d_in[0];
    const float* emb  = (const float*)d_in[1];
    const float* Wx   = (const float*)d_in[2];
    const float* Wc   = (const float*)d_in[3];
    const float* bias = (const float*)d_in[4];
    float* out = (float*)d_out;

    void *pA, *pB, *pG;
    cudaGetSymbolAddress(&pA, g_bufA);
    cudaGetSymbolAddress(&pB, g_bufB);
    cudaGetSymbolAddress(&pG, g_gx);
    float* bufA = (float*)pA;
    float* bufB = (float*)pB;
    float* gxp  = (float*)pG;

    static bool attr_set = false;
    if (!attr_set) {
        cudaFuncSetAttribute(scan_kernel, cudaFuncAttributeMaxDynamicSharedMemorySize, SCAN_SMEM);
        cudaFuncSetAttribute(mma_gemm_kernel, cudaFuncAttributeMaxDynamicSharedMemorySize, GEMM_SMEM);
        attr_set = true;
    }

    prep_kernel<<<128, 256>>>(xs);
    embed_kernel<<<CLB, 128>>>(emb);
    wsplit_kernel<<<dim3(48, 16, 4), dim3(32, 8)>>>(Wx);
    asplit_kernel<<<16384, 256>>>(bufA);     // layer-0 input split (scans produce the rest)

    dim3 ggrid(12, 256);

    const float* srcs[4] = {bufA, bufB, bufA, bufB};
    float*       dsts[4] = {bufB, bufA, bufB, out};
    int          revs[4] = {0, 1, 0, 1};

    for (int i = 0; i < 4; i++) {
        mma_gemm_kernel<<<ggrid, 256, GEMM_SMEM>>>(bias + i*1536, gxp, i);
        // flags advance 256 per block per step: scan i starts at i*512*256
        scan_kernel<<<64, 256, SCAN_SMEM>>>(srcs[i], gxp, Wc + (size_t)i*512*1024,
                                            dsts[i], revs[i], (unsigned)i * 131072u, i < 3 ? 1 : 0);
    }
}

// round 15
// speedup vs baseline: 1.6135x; 1.6135x over previous
#include <cuda_runtime.h>
#include <cuda_bf16.h>
#include <cstdint>

typedef unsigned long long ull;

#define CL 512
#define CB 64
#define CD 512
#define CLB (CL*CB)

// ---------------- scratch (static device allocations only) ----------------
__device__ float g_bufA[CLB*CD];              // activations ping (64 MB)
__device__ float g_bufB[CLB*CD];              // activations pong (64 MB)
__device__ float g_gx[(size_t)CLB*3*CD];      // gate pre-activations (192 MB)
__device__ __nv_bfloat16 g_chi[2][CB*CD];     // recurrent state bf16 hi, ping-pong
__device__ __nv_bfloat16 g_clo[2][CB*CD];     // recurrent state bf16 lo
__device__ float g_cfp[CB*CD];                // fp32 carry across scan launches
__device__ int   g_tok[CLB];
__device__ unsigned g_flag[4][32];            // per-(bg, block) step-completion flags
// bf16 split buffers for GEMM
__device__ ull g_Ahi[(size_t)CLB*CD/4];       // [32768,512] bf16
__device__ ull g_Alo[(size_t)CLB*CD/4];
__device__ ull g_Wthi[(size_t)4*1536*512/4];  // [4][1536][512] bf16 (W transposed)
__device__ ull g_Wtlo[(size_t)4*1536*512/4];

// ---------------- helpers ----------------
__device__ __forceinline__ unsigned ldacq(const unsigned* p){
    unsigned v; asm volatile("ld.acquire.gpu.u32 %0, [%1];" : "=r"(v) : "l"(p) : "memory"); return v;
}
__device__ __forceinline__ void red_rel_add(unsigned* p, unsigned v){
    asm volatile("red.add.release.gpu.u32 [%0], %1;" :: "l"(p), "r"(v) : "memory");
}
__device__ __forceinline__ float sigmoidf_(float x){ return 1.0f / (1.0f + __expf(-x)); }
__device__ __forceinline__ uint32_t smem_u32(const void* p){
    uint32_t a; asm("{ .reg .u64 t; cvta.to.shared.u64 t, %1; cvt.u32.u64 %0, t; }" : "=r"(a) : "l"(p));
    return a;
}
__device__ __forceinline__ void cpasync16(uint32_t dst, const void* src){
    asm volatile("cp.async.cg.shared.global [%0], [%1], 16;" :: "r"(dst), "l"(src));
}
__device__ __forceinline__ void cp_commit(){ asm volatile("cp.async.commit_group;" ::: "memory"); }
__device__ __forceinline__ void ldsm4(uint32_t addr, uint32_t* r){
    asm volatile("ldmatrix.sync.aligned.m8n8.x4.shared.b16 {%0,%1,%2,%3}, [%4];"
        : "=r"(r[0]),"=r"(r[1]),"=r"(r[2]),"=r"(r[3]) : "r"(addr));
}
__device__ __forceinline__ void ldsm2(uint32_t addr, uint32_t* r){
    asm volatile("ldmatrix.sync.aligned.m8n8.x2.shared.b16 {%0,%1}, [%2];"
        : "=r"(r[0]),"=r"(r[1]) : "r"(addr));
}
__device__ __forceinline__ void mma16816(float* d, const uint32_t* a, const uint32_t* b){
    asm volatile("mma.sync.aligned.m16n8k16.row.col.f32.bf16.bf16.f32 "
        "{%0,%1,%2,%3}, {%4,%5,%6,%7}, {%8,%9}, {%0,%1,%2,%3};"
        : "+f"(d[0]),"+f"(d[1]),"+f"(d[2]),"+f"(d[3])
        : "r"(a[0]),"r"(a[1]),"r"(a[2]),"r"(a[3]), "r"(b[0]),"r"(b[1]));
}

// ---------------- prep ----------------
__global__ void prep_kernel(const int* __restrict__ xs32) {
    __shared__ unsigned s_nz;
    int tid = threadIdx.x;
    if (tid == 0) s_nz = 0u;
    __syncthreads();
    unsigned nz = 0u;
    for (int i = tid; i < 1024; i += blockDim.x) nz |= (unsigned)xs32[2*i + 1];
    if (nz) atomicOr(&s_nz, 1u);
    __syncthreads();
    bool is64 = (s_nz == 0u);

    int stride = gridDim.x * blockDim.x;
    int gid = blockIdx.x * blockDim.x + tid;
    if (is64) {
        const long long* x64 = (const long long*)xs32;
        for (int i = gid; i < CLB; i += stride) g_tok[i] = (int)x64[i];
    } else {
        for (int i = gid; i < CLB; i += stride) g_tok[i] = xs32[i];
    }
    __nv_bfloat16 z = __float2bfloat16(0.0f);
    for (int i = gid; i < CB*CD; i += stride) {
        g_chi[0][i] = z; g_clo[0][i] = z; g_cfp[i] = 0.0f;
    }
    if (gid < 4*32) ((unsigned*)g_flag)[gid] = 0u;
}

// ---------------- embedding gather ----------------
__global__ void embed_kernel(const float* __restrict__ emb) {
    int row = blockIdx.x;
    int tok = g_tok[row];
    const float4* s = (const float4*)(emb + (size_t)tok * CD);
    float4* d = (float4*)(g_bufA + (size_t)row * CD);
    d[threadIdx.x] = s[threadIdx.x];
}

// ---------------- W transpose + bf16 hi/lo split (for GEMM) ----------------
__global__ void wsplit_kernel(const float* __restrict__ W) {
    __shared__ float t[32][33];
    int layer = blockIdx.z;
    int nt = blockIdx.x;
    int kt = blockIdx.y;
    int tx = threadIdx.x;
    __nv_bfloat16* Whi = (__nv_bfloat16*)g_Wthi;
    __nv_bfloat16* Wlo = (__nv_bfloat16*)g_Wtlo;
    for (int i = threadIdx.y; i < 32; i += 8)
        t[i][tx] = W[(size_t)layer*512*1536 + (size_t)(kt*32 + i)*1536 + nt*32 + tx];
    __syncthreads();
    for (int i = threadIdx.y; i < 32; i += 8) {
        float v = t[tx][i];
        __nv_bfloat16 h = __float2bfloat16(v);
        __nv_bfloat16 l = __float2bfloat16(v - __bfloat162float(h));
        size_t o = ((size_t)layer*1536 + nt*32 + i)*512 + kt*32 + tx;
        Whi[o] = h; Wlo[o] = l;
    }
}

// ---------------- A bf16 hi/lo split (layer-0 input only) ----------------
__global__ void asplit_kernel(const float* __restrict__ A) {
    size_t i = (size_t)blockIdx.x * blockDim.x + threadIdx.x;
    float4 v = ((const float4*)A)[i];
    __nv_bfloat16 h0 = __float2bfloat16(v.x), h1 = __float2bfloat16(v.y);
    __nv_bfloat16 h2 = __float2bfloat16(v.z), h3 = __float2bfloat16(v.w);
    __nv_bfloat162* Hi = (__nv_bfloat162*)g_Ahi;
    __nv_bfloat162* Lo = (__nv_bfloat162*)g_Alo;
    Hi[2*i]   = __nv_bfloat162(h0, h1);
    Hi[2*i+1] = __nv_bfloat162(h2, h3);
    Lo[2*i]   = __nv_bfloat162(__float2bfloat16(v.x - __bfloat162float(h0)),
                               __float2bfloat16(v.y - __bfloat162float(h1)));
    Lo[2*i+1] = __nv_bfloat162(__float2bfloat16(v.z - __bfloat162float(h2)),
                               __float2bfloat16(v.w - __bfloat162float(h3)));
}

// ---------------- mma.sync GEMM (3-term bf16 split) — proven R6 version ----------------
#define STAGE    65536
#define O_AHI    0
#define O_ALO    16384
#define O_WHI    32768
#define O_WLO    49152
#define GEMM_SMEM (2*STAGE + 1024)

__device__ __forceinline__ void load_stage(uint32_t sbuf,
        const __nv_bfloat16* Ah, const __nv_bfloat16* Al,
        const __nv_bfloat16* Wh, const __nv_bfloat16* Wl, int kc, int tid) {
    #pragma unroll
    for (int it = 0; it < 4; it++) {
        int c = tid + it*256;
        int row = c >> 3, seg = c & 7;
        uint32_t off = row*128 + seg*16;
        uint32_t sw  = off ^ ((off >> 3) & 0x70);
        size_t goff = (size_t)row*512 + kc*64 + seg*8;
        cpasync16(sbuf + O_AHI + sw, Ah + goff);
        cpasync16(sbuf + O_ALO + sw, Al + goff);
        cpasync16(sbuf + O_WHI + sw, Wh + goff);
        cpasync16(sbuf + O_WLO + sw, Wl + goff);
    }
}

__global__ __launch_bounds__(256, 1)
void mma_gemm_kernel(const float* __restrict__ bias, float* __restrict__ C, int layer) {
    extern __shared__ char gsm[];
    __shared__ float sbias[128];

    int tid = threadIdx.x;
    int lane = tid & 31;
    int warp = tid >> 5;
    int wm = warp >> 1;
    int wn = warp & 1;
    int bn = blockIdx.x;
    int bm = blockIdx.y;
    int m0 = bm * 128, n0 = bn * 128;

    uint32_t dynbase = (smem_u32(gsm) + 1023u) & ~1023u;

    const __nv_bfloat16* Ah = (const __nv_bfloat16*)g_Ahi + (size_t)m0 * 512;
    const __nv_bfloat16* Al = (const __nv_bfloat16*)g_Alo + (size_t)m0 * 512;
    const __nv_bfloat16* Wh = (const __nv_bfloat16*)g_Wthi + ((size_t)layer*1536 + n0) * 512;
    const __nv_bfloat16* Wl = (const __nv_bfloat16*)g_Wtlo + ((size_t)layer*1536 + n0) * 512;

    if (tid < 128) sbias[tid] = bias[n0 + tid];

    int a_rowin = (lane & 7) + ((lane >> 3) & 1) * 8;
    uint32_t a_kb_lane = (uint32_t)(lane >> 4) * 16;
    uint32_t a_rowb[2]; uint32_t a_s[2];
    #pragma unroll
    for (int t = 0; t < 2; t++) {
        uint32_t rb = (uint32_t)(wm*32 + t*16 + a_rowin) * 128;
        a_rowb[t] = rb;
        a_s[t] = (rb >> 3) & 0x70;
    }
    int b_rowin = lane & 7;
    uint32_t b_kb_lane = (uint32_t)((lane >> 3) & 1) * 16;
    uint32_t b_rowb[8]; uint32_t b_s[8];
    #pragma unroll
    for (int bt = 0; bt < 8; bt++) {
        uint32_t rb = (uint32_t)(wn*64 + bt*8 + b_rowin) * 128;
        b_rowb[bt] = rb;
        b_s[bt] = (rb >> 3) & 0x70;
    }

    float acc[2][8][4];
    #pragma unroll
    for (int t = 0; t < 2; t++)
        #pragma unroll
        for (int bt = 0; bt < 8; bt++)
            #pragma unroll
            for (int q = 0; q < 4; q++) acc[t][bt][q] = 0.0f;

    load_stage(dynbase, Ah, Al, Wh, Wl, 0, tid);
    cp_commit();

    for (int kc = 0; kc < 8; kc++) {
        uint32_t cbuf = dynbase + (kc & 1) * STAGE;
        if (kc < 7) {
            load_stage(dynbase + ((kc + 1) & 1) * STAGE, Ah, Al, Wh, Wl, kc + 1, tid);
            cp_commit();
            asm volatile("cp.async.wait_group 1;" ::: "memory");
        } else {
            asm volatile("cp.async.wait_group 0;" ::: "memory");
        }
        __syncthreads();

        #pragma unroll
        for (int ks = 0; ks < 4; ks++) {
            uint32_t akb = (uint32_t)ks*32 + a_kb_lane;
            uint32_t bkb = (uint32_t)ks*32 + b_kb_lane;
            uint32_t ah[2][4], al[2][4];
            #pragma unroll
            for (int t = 0; t < 2; t++) {
                uint32_t ao = a_rowb[t] + (akb ^ a_s[t]);
                ldsm4(cbuf + O_AHI + ao, ah[t]);
                ldsm4(cbuf + O_ALO + ao, al[t]);
            }
            uint32_t bh[8][2], bl[8][2];
            #pragma unroll
            for (int bt = 0; bt < 8; bt++) {
                uint32_t bo = b_rowb[bt] + (bkb ^ b_s[bt]);
                ldsm2(cbuf + O_WHI + bo, bh[bt]);
                ldsm2(cbuf + O_WLO + bo, bl[bt]);
            }
            #pragma unroll
            for (int t = 0; t < 2; t++)
                #pragma unroll
                for (int bt = 0; bt < 8; bt++) {
                    mma16816(acc[t][bt], ah[t], bh[bt]);
                    mma16816(acc[t][bt], ah[t], bl[bt]);
                    mma16816(acc[t][bt], al[t], bh[bt]);
                }
        }
        __syncthreads();
    }

    int r_in = lane >> 2;
    int c_in = 2 * (lane & 3);
    #pragma unroll
    for (int t = 0; t < 2; t++) {
        int row = m0 + wm*32 + t*16 + r_in;
        #pragma unroll
        for (int bt = 0; bt < 8; bt++) {
            int col = wn*64 + bt*8 + c_in;
            float b0 = sbias[col], b1 = sbias[col + 1];
            float2 o0 = make_float2(acc[t][bt][0] + b0, acc[t][bt][1] + b1);
            float2 o1 = make_float2(acc[t][bt][2] + b0, acc[t][bt][3] + b1);
            *(float2*)(C + (size_t)row * 1536 + n0 + col) = o0;
            *(float2*)(C + (size_t)(row + 8) * 1536 + n0 + col) = o1;
        }
    }
}

// ---------------- recurrent scan v9: R12 + one-step-ahead gx/x prefetch ----------------
// 128 blocks = 4 batch-groups (16 rows) x 32 d-groups (16 (i,f) pairs = 32 cols).
// 256 threads = 8 warps: wn = warp&3 (8 cols), wk = warp>>2 (256 k).
#define S_WHI 0
#define S_WLO (S_WHI + 32*1040)
#define S_CHI (S_WLO + 32*1040)
#define S_CLO (S_CHI + 16*1040)
#define S_RED (S_CLO + 16*1040)
#define SCAN_SMEM (S_RED + 2*16*33*4)

__global__ __launch_bounds__(256, 1)
void scan_kernel(const float* __restrict__ x_in, const float* __restrict__ gx,
                 const float* __restrict__ Wc, float* __restrict__ h_out,
                 int rev, unsigned cnt_base, int do_split) {
    extern __shared__ char smem[];
    uint32_t sb = smem_u32(smem);
    float* red = (float*)(smem + S_RED);

    int tid = threadIdx.x;
    int lane = tid & 31;
    int warp = tid >> 5;
    int wn = warp & 3;             // n-tile: cols wn*8..+7
    int wk = warp >> 2;            // k-half: k wk*256..+255
    int bg = blockIdx.x >> 5;
    int dg = blockIdx.x & 31;
    int r0 = bg * 16;
    int d0 = dg * 16;

    // ---- fill W slice (32 cols x 512 k), bf16 hi/lo, padded rows (once)
    {
        __nv_bfloat16* wh = (__nv_bfloat16*)(smem + S_WHI);
        __nv_bfloat16* wl = (__nv_bfloat16*)(smem + S_WLO);
        for (int idx = tid; idx < 32*512; idx += 256) {
            int col = idx >> 9, k = idx & 511;
            int gcol = (col < 16) ? (d0 + col) : (512 + d0 + col - 16);
            float v = Wc[(size_t)k * 1024 + gcol];
            __nv_bfloat16 h = __float2bfloat16(v);
            wh[col*520 + k] = h;
            wl[col*520 + k] = __float2bfloat16(v - __bfloat162float(h));
        }
    }

    // ldmatrix lane addressing (within padded tiles)
    int a_rowin = (lane & 7) + ((lane >> 3) & 1) * 8;   // 0..15
    uint32_t a_kb = (uint32_t)(lane >> 4) * 16;
    uint32_t aH0 = sb + S_CHI + (uint32_t)a_rowin*1040 + a_kb + (uint32_t)wk*512;
    uint32_t aL0 = sb + S_CLO + (uint32_t)a_rowin*1040 + a_kb + (uint32_t)wk*512;
    int b_rowin = lane & 7;
    uint32_t b_kb = (uint32_t)((lane >> 3) & 1) * 16;
    uint32_t bH0 = sb + S_WHI + (uint32_t)(wn*8 + b_rowin)*1040 + b_kb + (uint32_t)wk*512;
    uint32_t bL0 = sb + S_WLO + (uint32_t)(wn*8 + b_rowin)*1040 + b_kb + (uint32_t)wk*512;

    // epilogue mapping: thread -> one (row, d) element
    int erow = tid >> 4;
    int ej   = tid & 15;
    int eb   = r0 + erow;
    int ed   = d0 + ej;
    float creg = g_cfp[(size_t)eb * 512 + ed];    // fp32 carry from previous scan

    __nv_bfloat16* Ahi = (__nv_bfloat16*)g_Ahi;
    __nv_bfloat16* Alo = (__nv_bfloat16*)g_Alo;

    // ---- prologue: prefetch gx/x for step 0 (no dependency on flags)
    int tt0 = rev ? 511 : 0;
    size_t grow = (size_t)tt0 * CB + eb;
    float gi = gx[grow*1536 + ed];
    float gf = gx[grow*1536 + 512 + ed];
    float gc = gx[grow*1536 + 1024 + ed];
    float xv = x_in[grow*512 + ed];

    __syncthreads();

    for (int t = 0; t < 512; ++t) {
        int p  = t & 1;

        // ---- poll: all 32 blocks of this bg finished step t-1 (release-reduce flags)
        unsigned tgt = cnt_base + (unsigned)t * 256u;
        if (warp == 0) {
            while (__ballot_sync(0xffffffffu, ldacq(&g_flag[bg][lane]) < tgt) != 0u) {}
        }
        __syncthreads();

        // ---- stage c hi (group 0), then lo (group 1)
        {
            const char* srcH = (const char*)(g_chi[p]) + (size_t)r0 * 1024;
            #pragma unroll
            for (int it = 0; it < 4; it++) {
                int idx = tid + it*256;            // 0..1023
                int row = idx >> 6, seg = idx & 63;
                cpasync16(sb + S_CHI + (uint32_t)row*1040 + (uint32_t)seg*16,
                          srcH + (size_t)row*1024 + (size_t)seg*16);
            }
            cp_commit();
            const char* srcL = (const char*)(g_clo[p]) + (size_t)r0 * 1024;
            #pragma unroll
            for (int it = 0; it < 4; it++) {
                int idx = tid + it*256;
                int row = idx >> 6, seg = idx & 63;
                cpasync16(sb + S_CLO + (uint32_t)row*1040 + (uint32_t)seg*16,
                          srcL + (size_t)row*1024 + (size_t)seg*16);
            }
            cp_commit();
        }

        // ---- prefetch gx/x for step t+1 (full step of slack to cover DRAM)
        float gi_n = 0.f, gf_n = 0.f, gc_n = 0.f, xv_n = 0.f;
        size_t grow_n = 0;
        if (t < 511) {
            int tt1 = rev ? (510 - t) : (t + 1);
            grow_n = (size_t)tt1 * CB + eb;
            gi_n = gx[grow_n*1536 + ed];
            gf_n = gx[grow_n*1536 + 512 + ed];
            gc_n = gx[grow_n*1536 + 1024 + ed];
            xv_n = x_in[grow_n*512 + ed];
        }

        // ---- HI resident: run the two HI-dependent terms while LO drains
        asm volatile("cp.async.wait_group 1;" ::: "memory");
        __syncthreads();

        float accA[4] = {0,0,0,0}, accB[4] = {0,0,0,0}, accC[4] = {0,0,0,0};
        {
            uint32_t aH = aH0, bH = bH0, bL = bL0;
            #pragma unroll
            for (int kt = 0; kt < 16; kt++) {
                uint32_t ah[4], bh[2], bl[2];
                ldsm4(aH, ah);
                ldsm2(bH, bh);
                ldsm2(bL, bl);
                mma16816(accA, ah, bh);
                mma16816(accB, ah, bl);
                aH += 32; bH += 32; bL += 32;
            }
        }

        // ---- LO resident: third term
        asm volatile("cp.async.wait_group 0;" ::: "memory");
        __syncthreads();
        {
            uint32_t aL = aL0, bH = bH0;
            #pragma unroll
            for (int kt = 0; kt < 16; kt++) {
                uint32_t al[4], bh[2];
                ldsm4(aL, al);
                ldsm2(bH, bh);
                mma16816(accC, al, bh);
                aL += 32; bH += 32;
            }
        }
        {
            int r_in = lane >> 2;
            int c_in = 2 * (lane & 3);
            int col = wn*8 + c_in;
            float* rp = red + (size_t)wk * 16 * 33;
            rp[(r_in    )*33 + col    ] = accA[0] + accB[0] + accC[0];
            rp[(r_in    )*33 + col + 1] = accA[1] + accB[1] + accC[1];
            rp[(r_in + 8)*33 + col    ] = accA[2] + accB[2] + accC[2];
            rp[(r_in + 8)*33 + col + 1] = accA[3] + accB[3] + accC[3];
        }
        __syncthreads();

        // ---- epilogue: one output element per thread; c-store + release first
        {
            float pre_i = red[erow*33 + ej]      + red[16*33 + erow*33 + ej];
            float pre_f = red[erow*33 + 16 + ej] + red[16*33 + erow*33 + 16 + ej];
            float iv = sigmoidf_(gi + pre_i);
            float fv = sigmoidf_(gf + pre_f);
            float cn = iv * gc + fv * creg;
            creg = cn;
            __nv_bfloat16 ch = __float2bfloat16(cn);
            g_chi[p ^ 1][(size_t)eb * 512 + ed] = ch;
            g_clo[p ^ 1][(size_t)eb * 512 + ed] = __float2bfloat16(cn - __bfloat162float(ch));
            // release covers the two c stores; everything below is off the critical path
            red_rel_add(&g_flag[bg][dg], 1u);

            float hv = tanhf(cn) + xv;
            h_out[grow*512 + ed] = hv;
            if (t == 511) g_cfp[(size_t)eb * 512 + ed] = cn;
            if (do_split) {
                __nv_bfloat16 hh = __float2bfloat16(hv);
                Ahi[grow*512 + ed] = hh;
                Alo[grow*512 + ed] = __float2bfloat16(hv - __bfloat162float(hh));
            }
        }

        // rotate prefetched operands
        gi = gi_n; gf = gf_n; gc = gc_n; xv = xv_n; grow = grow_n;
    }
}

// ---------------- driver ----------------
extern "C" void kernel_launch(void* const* d_in, const int* in_sizes, int n_in,
                              void* d_out, int out_size) {
    const int*   xs   = (const int*)  d_in[0];
    const float* emb  = (const float*)d_in[1];
    const float* Wx   = (const float*)d_in[2];
    const float* Wc   = (const float*)d_in[3];
    const float* bias = (const float*)d_in[4];
    float* out = (float*)d_out;

    void *pA, *pB, *pG;
    cudaGetSymbolAddress(&pA, g_bufA);
    cudaGetSymbolAddress(&pB, g_bufB);
    cudaGetSymbolAddress(&pG, g_gx);
    float* bufA = (float*)pA;
    float* bufB = (float*)pB;
    float* gxp  = (float*)pG;

    static bool attr_set = false;
    if (!attr_set) {
        cudaFuncSetAttribute(scan_kernel, cudaFuncAttributeMaxDynamicSharedMemorySize, SCAN_SMEM);
        cudaFuncSetAttribute(mma_gemm_kernel, cudaFuncAttributeMaxDynamicSharedMemorySize, GEMM_SMEM);
        attr_set = true;
    }

    prep_kernel<<<128, 256>>>(xs);
    embed_kernel<<<CLB, 128>>>(emb);
    wsplit_kernel<<<dim3(48, 16, 4), dim3(32, 8)>>>(Wx);
    asplit_kernel<<<16384, 256>>>(bufA);     // layer-0 input split (scans produce the rest)

    dim3 ggrid(12, 256);

    const float* srcs[4] = {bufA, bufB, bufA, bufB};
    float*       dsts[4] = {bufB, bufA, bufB, out};
    int          revs[4] = {0, 1, 0, 1};

    for (int i = 0; i < 4; i++) {
        mma_gemm_kernel<<<ggrid, 256, GEMM_SMEM>>>(bias + i*1536, gxp, i);
        // flags advance 256 per block per step: scan i starts at i*512*256
        scan_kernel<<<128, 256, SCAN_SMEM>>>(srcs[i], gxp, Wc + (size_t)i*512*1024,
                                             dsts[i], revs[i], (unsigned)i * 131072u, i < 3 ? 1 : 0);
    }
}